// round 12
// baseline (speedup 1.0000x reference)
#include <cuda_runtime.h>
#include <cuda_bf16.h>

// GraphGather / segment_sum, single kernel, atomic-free, zero-pass-free:
//   out[b, :] = sum of feats[a, :] for membership[a] == b
// feats: [524288, 128] f32, membership: [524288] i32 (SORTED), out: [16384, 128] f32.
//
// R12: warp-per-segment with INLINE warp-cooperative range finding.
//  - start = lower_bound(memb, seg): 32-ary ballot search, 3 rounds + final
//    scan (524288 -> 16384 -> 512 -> 16 -> exact), coalesced probes, L2-hot.
//  - end: gallop 32 rows/probe from start (expected ~1.2 probes, len~32).
//  - stream: unconditional 8-deep float4 batches (MLP_p1=8, evict-first)
//    + one predicated remainder batch.
//  - exactly one plain STG.128 per lane per output row: overwrites the
//    poisoned output, idempotent across graph replays, empty segs -> zeros.
//  - no atomics, no zero kernel, no prepass, one graph node.

#define N_FEAT 128
#define FEAT4 (N_FEAT / 4)       // 32 float4 per row
#define TPB 256

__global__ __launch_bounds__(TPB)
void gg_fused_kernel(const float4* __restrict__ feats,
                     const int* __restrict__ memb,
                     float4* __restrict__ out,
                     int n_atoms, int batch) {
    const int seg = (blockIdx.x * TPB + threadIdx.x) >> 5;   // warp id = segment
    const int lane = threadIdx.x & 31;
    const unsigned FULL = 0xFFFFFFFFu;
    if (seg >= batch) return;

    // ---- start = lower_bound(memb, seg): warp-cooperative 32-ary search ----
    // Invariant: lb in [lo, lo+len].
    int lo = 0;
    int len = n_atoms;
    while (len > 32) {
        int stride = (len + 31) >> 5;                 // ceil(len/32) >= 2
        bool inwin = (lane * stride) < len;
        bool pred = inwin && (__ldg(memb + lo + lane * stride) < seg);
        int cnt = __popc(__ballot_sync(FULL, pred));  // prefix-true count
        int nprobe = min(32, (len + stride - 1) / stride);
        int newlo = (cnt == 0) ? lo : lo + (cnt - 1) * stride + 1;
        int newhi = (cnt == nprobe) ? lo + len : lo + cnt * stride;
        lo = newlo;
        len = newhi - newlo;
    }
    {
        bool pred = (lane < len) && (__ldg(memb + lo + lane) < seg);
        lo += __popc(__ballot_sync(FULL, pred));
    }
    const int start = lo;

    // ---- end = lower_bound(memb, seg+1): gallop from start ----
    int end = start;
    while (end < n_atoms) {
        int idx = end + lane;
        bool gt = (idx >= n_atoms) || (__ldg(memb + idx) > seg);
        unsigned bal = __ballot_sync(FULL, gt);
        if (bal) { end += __ffs(bal) - 1; break; }
        end += 32;
    }
    const int nrows = end - start;

    // ---- stream rows [start, end): lane l owns float4 column l ----
    const float4* base = feats + (size_t)start * FEAT4 + lane;
    float4 acc = make_float4(0.f, 0.f, 0.f, 0.f);

    const int nfull = nrows >> 3;     // unconditional 8-deep batches
    for (int bt = 0; bt < nfull; ++bt) {
        float4 v[8];
        #pragma unroll
        for (int i = 0; i < 8; ++i)
            v[i] = __ldcs(base + (size_t)(bt * 8 + i) * FEAT4);
        #pragma unroll
        for (int i = 0; i < 8; ++i) {
            acc.x += v[i].x; acc.y += v[i].y;
            acc.z += v[i].z; acc.w += v[i].w;
        }
    }
    const int rem = nrows & 7;        // one predicated remainder batch
    if (rem) {
        const float4 z = make_float4(0.f, 0.f, 0.f, 0.f);
        float4 v[8];
        #pragma unroll
        for (int i = 0; i < 8; ++i) {
            int r = nfull * 8 + i;
            v[i] = (i < rem) ? __ldcs(base + (size_t)r * FEAT4) : z;
        }
        #pragma unroll
        for (int i = 0; i < 8; ++i) {
            acc.x += v[i].x; acc.y += v[i].y;
            acc.z += v[i].z; acc.w += v[i].w;
        }
    }

    // One plain coalesced 16B store per lane; empty segments write zeros.
    out[(size_t)seg * FEAT4 + lane] = acc;
}

extern "C" void kernel_launch(void* const* d_in, const int* in_sizes, int n_in,
                              void* d_out, int out_size) {
    const float* feats = (const float*)d_in[0];
    const int* memb = (const int*)d_in[1];
    float* out = (float*)d_out;

    const int n_atoms = in_sizes[1];          // 524288
    const int batch = out_size / N_FEAT;      // 16384

    const int n_warps = batch;                // one warp per segment
    const int blocks = (n_warps + (TPB / 32) - 1) / (TPB / 32);
    gg_fused_kernel<<<blocks, TPB>>>((const float4*)feats, memb,
                                     (float4*)out, n_atoms, batch);
}